// round 5
// baseline (speedup 1.0000x reference)
#include <cuda_runtime.h>

#define POOL 14
#define H 128
#define W 128
#define C 1024
#define R 256
#define C4 (C / 4)

// One CTA per (roi, py) row; 256 threads = one float4 channel-group each.
// Structure identical to the best (R2) kernel -- full unroll, straight
// batched LDG.128 -- plus two *uniform* load eliminations:
//   1. fy==0 or ay1==ay0 is constant per CTA -> branch once into an
//      x-lerp-only loop (2 loads/px instead of 4). ~26% of CTAs.
//   2. px==0 always has fx==0 (src_x = 0*w/14) -> peeled statically:
//      2 loads (full path) / 1 load (x-only path).
// All eliminations are bit-exact (zero-weight or duplicate-address terms).
__global__ __launch_bounds__(256) void roi_resize_kernel(
    const float4* __restrict__ img,   // [H, W, C4]
    const float*  __restrict__ rois,  // [R, 4]
    float4*       __restrict__ out)   // [R, POOL, POOL, C4]
{
    const int py = blockIdx.x;          // 0..13
    const int r  = blockIdx.y;          // 0..255
    const int c4 = threadIdx.x;         // 0..255

    __shared__ int   s_ax0[POOL];
    __shared__ int   s_ax1[POOL];
    __shared__ float s_fx [POOL];

    const int x1 = (int)rois[r * 4 + 0];
    const int y1 = (int)rois[r * 4 + 1];
    const int x2 = (int)rois[r * 4 + 2];
    const int y2 = (int)rois[r * 4 + 3];

    if (threadIdx.x < POOL) {
        const float ww = (float)(x2 - x1);
        const float src_x = (float)threadIdx.x * (ww * (1.0f / POOL));
        const int   x0 = (int)floorf(src_x);
        const int   x1i = min(x0 + 1, (x2 - x1) - 1);
        s_fx [threadIdx.x] = src_x - (float)x0;
        s_ax0[threadIdx.x] = min(max(x1 + x0, 0), W - 1);
        s_ax1[threadIdx.x] = min(max(x1 + x1i, 0), W - 1);
    }

    const float hh = (float)(y2 - y1);
    const float src_y = (float)py * (hh * (1.0f / POOL));
    const int   y0 = (int)floorf(src_y);
    const float fy = src_y - (float)y0;
    const int   y1i = min(y0 + 1, (y2 - y1) - 1);
    const int   ay0 = min(max(y1 + y0, 0), H - 1);
    const int   ay1 = min(max(y1 + y1i, 0), H - 1);

    __syncthreads();

    const float4* __restrict__ row0 = img + (size_t)(ay0 * W) * C4 + c4;
    const float4* __restrict__ row1 = img + (size_t)(ay1 * W) * C4 + c4;
    float4* __restrict__ orow = out + ((size_t)(r * POOL + py) * POOL) * C4 + c4;

    // CTA-uniform: does row1 contribute at all?
    const bool needy = (fy != 0.0f) && (ay1 != ay0);

    if (needy) {
        // ---- full bilinear path ----
        // px = 0 peeled: fx == 0 exactly -> o = v00 + (v10 - v00) * fy
        {
            const int ax0 = s_ax0[0];
            const float4 v00 = row0[ax0 * C4];
            const float4 v10 = row1[ax0 * C4];
            float4 o;
            o.x = v00.x + (v10.x - v00.x) * fy;
            o.y = v00.y + (v10.y - v00.y) * fy;
            o.z = v00.z + (v10.z - v00.z) * fy;
            o.w = v00.w + (v10.w - v00.w) * fy;
            __stcs(&orow[0], o);
        }
        #pragma unroll
        for (int px = 1; px < POOL; px++) {
            const int   ax0 = s_ax0[px];
            const int   ax1 = s_ax1[px];
            const float fx  = s_fx[px];

            const float4 v00 = row0[ax0 * C4];
            const float4 v01 = row0[ax1 * C4];
            const float4 v10 = row1[ax0 * C4];
            const float4 v11 = row1[ax1 * C4];

            float4 o;
            {
                float top = v00.x + (v01.x - v00.x) * fx;
                float bot = v10.x + (v11.x - v10.x) * fx;
                o.x = top + (bot - top) * fy;
            }
            {
                float top = v00.y + (v01.y - v00.y) * fx;
                float bot = v10.y + (v11.y - v10.y) * fx;
                o.y = top + (bot - top) * fy;
            }
            {
                float top = v00.z + (v01.z - v00.z) * fx;
                float bot = v10.z + (v11.z - v10.z) * fx;
                o.z = top + (bot - top) * fy;
            }
            {
                float top = v00.w + (v01.w - v00.w) * fx;
                float bot = v10.w + (v11.w - v10.w) * fx;
                o.w = top + (bot - top) * fy;
            }
            __stcs(&orow[(size_t)px * C4], o);
        }
    } else {
        // ---- x-lerp-only path (row1 term is exactly zero / duplicate) ----
        // px = 0 peeled: fx == 0 and fy-term dead -> o = v00
        {
            const float4 v00 = row0[s_ax0[0] * C4];
            __stcs(&orow[0], v00);
        }
        #pragma unroll
        for (int px = 1; px < POOL; px++) {
            const int   ax0 = s_ax0[px];
            const int   ax1 = s_ax1[px];
            const float fx  = s_fx[px];

            const float4 v00 = row0[ax0 * C4];
            const float4 v01 = row0[ax1 * C4];

            float4 o;
            o.x = v00.x + (v01.x - v00.x) * fx;
            o.y = v00.y + (v01.y - v00.y) * fx;
            o.z = v00.z + (v01.z - v00.z) * fx;
            o.w = v00.w + (v01.w - v00.w) * fx;
            __stcs(&orow[(size_t)px * C4], o);
        }
    }
}

extern "C" void kernel_launch(void* const* d_in, const int* in_sizes, int n_in,
                              void* d_out, int out_size) {
    const float4* img  = (const float4*)d_in[0];
    const float*  rois = (const float*)d_in[1];
    float4*       out  = (float4*)d_out;

    dim3 grid(POOL, R);
    roi_resize_kernel<<<grid, 256>>>(img, rois, out);
}

// round 6
// speedup vs baseline: 1.4991x; 1.4991x over previous
#include <cuda_runtime.h>

#define POOL 14
#define H 128
#define W 128
#define C 1024
#define R 256
#define C4 (C / 4)

// Exact R2 structure (best measured: 55.1us): one CTA per (roi, py) row,
// 256 threads = one float4 channel-group each, x-side tuples in shared,
// full 14-px unroll, 4 straight LDG.128 + lerp + streaming STG.128.
//
// R6 delta (precompute-only, inner loop byte-identical):
//  - fx==0  -> alias s_ax1[px] = s_ax0[px]: the v01/v11 loads hit the line
//    v00/v10 just brought into L1 (L1 hit instead of L2 hit). Bit-exact,
//    the fx-weighted term is zero.
//  - fy==0 or ay1==ay0 (CTA-uniform) -> alias row1 = row0 via one pointer
//    select: v10/v11 become L1 hits. Bit-exact.
// ~25% of corner reads convert from ~250cyc L2 hits to ~39cyc L1 hits and
// L2 read traffic drops ~25%, with zero added inner-loop instructions.
__global__ __launch_bounds__(256) void roi_resize_kernel(
    const float4* __restrict__ img,   // [H, W, C4]
    const float*  __restrict__ rois,  // [R, 4]
    float4*       __restrict__ out)   // [R, POOL, POOL, C4]
{
    const int py = blockIdx.x;          // 0..13
    const int r  = blockIdx.y;          // 0..255
    const int c4 = threadIdx.x;         // 0..255

    __shared__ int   s_ax0[POOL];
    __shared__ int   s_ax1[POOL];
    __shared__ float s_fx [POOL];

    const int x1 = (int)rois[r * 4 + 0];
    const int y1 = (int)rois[r * 4 + 1];
    const int x2 = (int)rois[r * 4 + 2];
    const int y2 = (int)rois[r * 4 + 3];

    if (threadIdx.x < POOL) {
        const float ww = (float)(x2 - x1);
        const float src_x = (float)threadIdx.x * (ww * (1.0f / POOL));
        const int   x0 = (int)floorf(src_x);
        const int   x1i = min(x0 + 1, (x2 - x1) - 1);
        const float fx = src_x - (float)x0;
        const int   ax0 = min(max(x1 + x0, 0), W - 1);
        int         ax1 = min(max(x1 + x1i, 0), W - 1);
        if (fx == 0.0f) ax1 = ax0;      // zero-weight corner -> alias address
        s_fx [threadIdx.x] = fx;
        s_ax0[threadIdx.x] = ax0;
        s_ax1[threadIdx.x] = ax1;
    }

    const float hh = (float)(y2 - y1);
    const float src_y = (float)py * (hh * (1.0f / POOL));
    const int   y0 = (int)floorf(src_y);
    const float fy = src_y - (float)y0;
    const int   y1i = min(y0 + 1, (y2 - y1) - 1);
    const int   ay0 = min(max(y1 + y0, 0), H - 1);
    int         ay1 = min(max(y1 + y1i, 0), H - 1);
    if (fy == 0.0f) ay1 = ay0;          // zero-weight row -> alias address

    __syncthreads();

    const float4* __restrict__ row0 = img + (size_t)(ay0 * W) * C4 + c4;
    const float4* __restrict__ row1 = img + (size_t)(ay1 * W) * C4 + c4;
    float4* __restrict__ orow = out + ((size_t)(r * POOL + py) * POOL) * C4 + c4;

    #pragma unroll
    for (int px = 0; px < POOL; px++) {
        const int   ax0 = s_ax0[px];
        const int   ax1 = s_ax1[px];
        const float fx  = s_fx[px];

        const float4 v00 = row0[ax0 * C4];
        const float4 v01 = row0[ax1 * C4];
        const float4 v10 = row1[ax0 * C4];
        const float4 v11 = row1[ax1 * C4];

        float4 o;
        {
            float top = v00.x + (v01.x - v00.x) * fx;
            float bot = v10.x + (v11.x - v10.x) * fx;
            o.x = top + (bot - top) * fy;
        }
        {
            float top = v00.y + (v01.y - v00.y) * fx;
            float bot = v10.y + (v11.y - v10.y) * fx;
            o.y = top + (bot - top) * fy;
        }
        {
            float top = v00.z + (v01.z - v00.z) * fx;
            float bot = v10.z + (v11.z - v10.z) * fx;
            o.z = top + (bot - top) * fy;
        }
        {
            float top = v00.w + (v01.w - v00.w) * fx;
            float bot = v10.w + (v11.w - v10.w) * fx;
            o.w = top + (bot - top) * fy;
        }

        __stcs(&orow[(size_t)px * C4], o);
    }
}

extern "C" void kernel_launch(void* const* d_in, const int* in_sizes, int n_in,
                              void* d_out, int out_size) {
    const float4* img  = (const float4*)d_in[0];
    const float*  rois = (const float*)d_in[1];
    float4*       out  = (float4*)d_out;

    dim3 grid(POOL, R);
    roi_resize_kernel<<<grid, 256>>>(img, rois, out);
}